// round 16
// baseline (speedup 1.0000x reference)
#include <cuda_runtime.h>
#include <cuda_fp16.h>
#include <math.h>
#include <stdint.h>

// Problem dims (fixed)
#define KENT    8
#define BENT    4096
#define MDIM    4096
#define HIN     512
#define HENC    256
#define HCORE   512
#define HCTX    256
#define HSTATE  512
#define NPAIR   (BENT * (KENT - 1))   // 28672
#define HTOT    (HENC + HCTX + HIN)   // 1024

// ---- scratch (no allocation allowed) ----
__device__ __half g_inh[(size_t)BENT * MDIM];
__device__ __half g_sth[BENT * HSTATE];
__device__ __half g_Winh[MDIM * HIN];
__device__ __half g_Wench[HSTATE * HENC];
__device__ __half g_Wcath[HENC * (2 * HCORE)];     // [256,1024] = [Wtop | Wbot]
__device__ __half g_Wctxh[HCORE * HCTX];
__device__ __half g_Wrech[HTOT * HSTATE];
__device__ __half g_Wouth[HSTATE * MDIM];
__device__ __half g_Xh[BENT * HIN];
__device__ __half g_S1h[BENT * HENC];
__device__ __half g_CFh[(size_t)BENT * 2 * HCORE]; // [4096,1024] fp16, 8 MB
__device__ __half g_coreh[(size_t)NPAIR * HCORE];
__device__ __half g_ctxh[(size_t)NPAIR * HCTX];
__device__ float  g_att[NPAIR];
__device__ __half g_Th[BENT * HTOT];
__device__ __half g_NSh[BENT * HSTATE];

template<int ACT>
__device__ __forceinline__ float actf(float v) {
    if (ACT == 1) return fmaxf(v, 0.0f);                  // relu
    if (ACT == 2) return 1.0f / (1.0f + expf(-v));        // sigmoid
    if (ACT == 3) return v > 0.0f ? v : expm1f(v);        // elu
    return v;                                             // 0: identity (no bias)
}

// ---- fused fp32->fp16 conversion over 8 fixed segments ----
// seg 4 (W_core) repacked: row k (0..511), col n -> Wcat[(k&255)*1024 + (k>>8)*512 + n]
struct CvtArgs { const float* s[8]; __half* d[8]; };

__global__ void __launch_bounds__(256)
cvtall_k(CvtArgs a)
{
    long long i = ((long long)blockIdx.x * 256 + threadIdx.x) * 8;
    int seg; long long off;
    if      (i < 16777216LL) { seg = 0; off = i; }
    else if (i < 18874368LL) { seg = 1; off = i - 16777216LL; }
    else if (i < 20971520LL) { seg = 2; off = i - 18874368LL; }
    else if (i < 21102592LL) { seg = 3; off = i - 20971520LL; }
    else if (i < 21364736LL) { seg = 4; off = i - 21102592LL; }
    else if (i < 21495808LL) { seg = 5; off = i - 21364736LL; }
    else if (i < 22020096LL) { seg = 6; off = i - 21495808LL; }
    else if (i < 24117248LL) { seg = 7; off = i - 22020096LL; }
    else return;
    const float* s = a.s[seg] + off;
    long long doff = off;
    if (seg == 4) {
        long long k = off >> 9, n = off & 511;
        doff = (k & 255) * 1024 + (k >> 8) * 512 + n;
    }
    __half* d = a.d[seg] + doff;
    float4 x = *(const float4*)s;
    float4 y = *(const float4*)(s + 4);
    __half2 h0 = __floats2half2_rn(x.x, x.y);
    __half2 h1 = __floats2half2_rn(x.z, x.w);
    __half2 h2 = __floats2half2_rn(y.x, y.y);
    __half2 h3 = __floats2half2_rn(y.z, y.w);
    uint4 o;
    o.x = *(uint32_t*)&h0; o.y = *(uint32_t*)&h1;
    o.z = *(uint32_t*)&h2; o.w = *(uint32_t*)&h3;
    *(uint4*)d = o;
}

// ---- GEMM tiling (proven): BK=32, 4-stage cp.async pipeline ----
#define STAGES 4
#define ASTR 80
#define BSTR 272
#define BBUF (32 * BSTR)              // 8704
#define ABUF (128 * ASTR)             // 10240
#define STGB (ABUF + BBUF)
#define SMEMG (STAGES * STGB)         // 75776

__device__ __forceinline__ void cp16(uint32_t dst, const void* src) {
    asm volatile("cp.async.cg.shared.global [%0], [%1], 16;" :: "r"(dst), "l"(src));
}

// fp16 tensor-core GEMM body. 128x128 CTA tile, BK=32, 256 threads, 8 warps
// 2x4, warp tile 64x32 (m16n8k16), fp32 accum.
// ACT 0: identity, NO bias. WOUT 0: fp16 C. 1: fp32 C. 2: both.
template<int ACT, int WOUT>
__device__ __forceinline__ void
hgemm_dev(const __half* __restrict__ A, const __half* __restrict__ B,
          const float* __restrict__ bias, __half* __restrict__ Ch,
          float* __restrict__ Cf, int N, int K, int bx, int by, char* sm)
{
    const uint32_t smb = (uint32_t)__cvta_generic_to_shared(sm);

    const int tid  = threadIdx.x;
    const int warp = tid >> 5;
    const int lane = tid & 31;
    const int row0 = by * 128;
    const int col0 = bx * 128;

    const int wm = warp >> 2, wn = warp & 3;
    const int m_base = wm * 64, n_base = wn * 32;
    const int grp = lane >> 2, tg = lane & 3;

    const int a_row = (lane & 7) + ((lane >> 3) & 1) * 8;
    const int a_kh  = (lane >> 4) * 8;
    const uint32_t aLane = (uint32_t)((m_base + a_row) * ASTR + a_kh * 2);
    const int b_k  = (lane & 7) + ((lane >> 3) & 1) * 8;
    const int b_nh = (lane >> 4) * 8;
    const uint32_t bLane = (uint32_t)(b_k * BSTR + (n_base + b_nh) * 2);

    const int arow = tid >> 1;
    const int ak16 = (tid & 1) * 16;
    const uint32_t aoff = (uint32_t)(arow * ASTR + ak16 * 2);
    const __half* aBase = A + (size_t)(row0 + arow) * K + ak16;
    const int brow = tid >> 3;
    const int bo16 = (tid & 7) * 16;
    const uint32_t boff = (uint32_t)(brow * BSTR + bo16 * 2);
    const __half* bBase = B + (size_t)brow * N + col0 + bo16;

    auto issue_stage = [&](int s, int kg) {
        uint32_t ab = smb + (uint32_t)s * STGB;
        uint32_t bb = ab + ABUF;
        const __half* asrc = aBase + kg;
        cp16(ab + aoff, asrc);
        cp16(ab + aoff + 16, asrc + 8);
        const __half* bsrc = bBase + (size_t)kg * N;
        cp16(bb + boff, bsrc);
        cp16(bb + boff + 16, bsrc + 8);
    };

    float acc[4][4][4];
#pragma unroll
    for (int mt = 0; mt < 4; mt++)
#pragma unroll
        for (int nt = 0; nt < 4; nt++)
#pragma unroll
            for (int c = 0; c < 4; c++) acc[mt][nt][c] = 0.0f;

    const int nk = K >> 5;

#pragma unroll
    for (int s = 0; s < STAGES - 1; s++) {
        if (s < nk) issue_stage(s, s << 5);
        asm volatile("cp.async.commit_group;" ::: "memory");
    }

    for (int it = 0; it < nk; ++it) {
        asm volatile("cp.async.wait_group %0;" :: "n"(STAGES - 2) : "memory");
        __syncthreads();
        const int nxt = it + STAGES - 1;
        if (nxt < nk) issue_stage(nxt & (STAGES - 1), nxt << 5);
        asm volatile("cp.async.commit_group;" ::: "memory");

        const uint32_t ab = smb + (uint32_t)(it & (STAGES - 1)) * STGB + aLane;
        const uint32_t bb = smb + (uint32_t)(it & (STAGES - 1)) * STGB + ABUF + bLane;
#pragma unroll
        for (int ks = 0; ks < 2; ks++) {
            uint32_t af[4][4];
#pragma unroll
            for (int mt = 0; mt < 4; mt++) {
                uint32_t addr = ab + mt * (16 * ASTR) + ks * 32;
                asm volatile("ldmatrix.sync.aligned.m8n8.x4.shared.b16 {%0,%1,%2,%3}, [%4];"
                             : "=r"(af[mt][0]), "=r"(af[mt][1]),
                               "=r"(af[mt][2]), "=r"(af[mt][3])
                             : "r"(addr));
            }
            uint32_t bf[4][2];
#pragma unroll
            for (int nl = 0; nl < 2; nl++) {
                uint32_t addr = bb + nl * 32 + ks * (16 * BSTR);
                asm volatile("ldmatrix.sync.aligned.m8n8.x4.trans.shared.b16 {%0,%1,%2,%3}, [%4];"
                             : "=r"(bf[nl*2][0]), "=r"(bf[nl*2][1]),
                               "=r"(bf[nl*2+1][0]), "=r"(bf[nl*2+1][1])
                             : "r"(addr));
            }
#pragma unroll
            for (int mt = 0; mt < 4; mt++) {
#pragma unroll
                for (int nt = 0; nt < 4; nt++) {
                    asm("mma.sync.aligned.m16n8k16.row.col.f32.f16.f16.f32 "
                        "{%0,%1,%2,%3}, {%4,%5,%6,%7}, {%8,%9}, {%0,%1,%2,%3};"
                        : "+f"(acc[mt][nt][0]), "+f"(acc[mt][nt][1]),
                          "+f"(acc[mt][nt][2]), "+f"(acc[mt][nt][3])
                        : "r"(af[mt][0]), "r"(af[mt][1]), "r"(af[mt][2]), "r"(af[mt][3]),
                          "r"(bf[nt][0]), "r"(bf[nt][1]));
                }
            }
        }
    }

#pragma unroll
    for (int nt = 0; nt < 4; nt++) {
        int col = col0 + n_base + nt * 8 + 2 * tg;
        float2 bb2;
        if (ACT == 0) { bb2.x = 0.0f; bb2.y = 0.0f; }
        else          { bb2 = *(const float2*)(bias + col); }
#pragma unroll
        for (int mt = 0; mt < 4; mt++) {
            int row = row0 + m_base + mt * 16 + grp;
            float v00 = actf<ACT>(acc[mt][nt][0] + bb2.x);
            float v01 = actf<ACT>(acc[mt][nt][1] + bb2.y);
            float v10 = actf<ACT>(acc[mt][nt][2] + bb2.x);
            float v11 = actf<ACT>(acc[mt][nt][3] + bb2.y);
            if (WOUT != 1) {
                __half2 h0 = __floats2half2_rn(v00, v01);
                __half2 h1 = __floats2half2_rn(v10, v11);
                *(__half2*)(Ch + (size_t)row * N + col) = h0;
                *(__half2*)(Ch + (size_t)(row + 8) * N + col) = h1;
            }
            if (WOUT != 0) {
                float2 f0 = {v00, v01}, f1 = {v10, v11};
                *(float2*)(Cf + (size_t)row * N + col) = f0;
                *(float2*)(Cf + (size_t)(row + 8) * N + col) = f1;
            }
        }
    }
}

// standalone wrapper
template<int ACT, int WOUT>
__global__ void __launch_bounds__(256, 2)
hgemm_g(const __half* __restrict__ A, const __half* __restrict__ B,
        const float* __restrict__ bias, __half* __restrict__ Ch,
        float* __restrict__ Cf, int N, int K)
{
    extern __shared__ char sm[];
    hgemm_dev<ACT, WOUT>(A, B, bias, Ch, Cf, N, K, blockIdx.x, blockIdx.y, sm);
}

// fused: X GEMM FIRST (blocks 0..127: 4 x 32, long K=4096, lands 1/SM in
// wave 1) + ctx GEMM (blocks 128..575: 2 x 224, short K=512, backfills).
__global__ void __launch_bounds__(256, 2)
fused_xc(const __half* __restrict__ inh, const __half* __restrict__ Winh,
         const float* __restrict__ bin, __half* __restrict__ Xh,
         const __half* __restrict__ core, const __half* __restrict__ Wctx,
         const float* __restrict__ bctx, __half* __restrict__ ctxh)
{
    extern __shared__ char sm[];
    int b = blockIdx.x;
    if (b < 128) {
        hgemm_dev<3, 0>(inh, Winh, bin, Xh, nullptr, HIN, MDIM,
                        b & 3, b >> 2, sm);
    } else {
        b -= 128;
        hgemm_dev<1, 0>(core, Wctx, bctx, ctxh, nullptr, HCTX, HCORE,
                        b & 1, b >> 1, sm);
    }
}

// gather + attention from fp16 CF, vectorized: 128 threads, 4 elems/thread.
__global__ void __launch_bounds__(128)
gath_k(const __half* __restrict__ CF, const float* __restrict__ b_core,
       const float* __restrict__ W_att, const float* __restrict__ b_att,
       __half* __restrict__ core, float* __restrict__ att)
{
    __shared__ float red[4];
    int p = blockIdx.x;
    int t = threadIdx.x;
    int b_ = p / 56, rem = p % 56;
    int i_ = rem / 7, jj = rem % 7;
    int j_ = jj + (jj >= i_ ? 1 : 0);
    const __half* crow = CF + (size_t)(b_ * KENT + j_) * 1024;
    const __half* frow = CF + (size_t)(b_ * KENT + i_) * 1024 + 512;

    uint2 cu = *(const uint2*)(crow + 4 * t);
    uint2 fu = *(const uint2*)(frow + 4 * t);
    float2 c0 = __half22float2(*(__half2*)&cu.x);
    float2 c1 = __half22float2(*(__half2*)&cu.y);
    float2 f0 = __half22float2(*(__half2*)&fu.x);
    float2 f1 = __half22float2(*(__half2*)&fu.y);
    float4 bb = *(const float4*)(b_core + 4 * t);
    float v0 = fmaxf(c0.x + f0.x + bb.x, 0.0f);
    float v1 = fmaxf(c0.y + f0.y + bb.y, 0.0f);
    float v2 = fmaxf(c1.x + f1.x + bb.z, 0.0f);
    float v3 = fmaxf(c1.y + f1.y + bb.w, 0.0f);
    __half2 o0 = __floats2half2_rn(v0, v1);
    __half2 o1 = __floats2half2_rn(v2, v3);
    uint2 ov;
    ov.x = *(uint32_t*)&o0; ov.y = *(uint32_t*)&o1;
    *(uint2*)(core + (size_t)p * HCORE + 4 * t) = ov;

    float4 w = *(const float4*)(W_att + 4 * t);
    float s = v0 * w.x + v1 * w.y + v2 * w.z + v3 * w.w;
#pragma unroll
    for (int o = 16; o; o >>= 1) s += __shfl_xor_sync(0xFFFFFFFFu, s, o);
    int warp = t >> 5;
    if ((t & 31) == 0) red[warp] = s;
    __syncthreads();
    if (t == 0) {
        float tot = red[0] + red[1] + red[2] + red[3];
        att[p] = 1.0f / (1.0f + expf(-(tot + b_att[0])));
    }
}

// fused: E = sum_j att*ctx, then T = [S1 | E | X]
__global__ void __launch_bounds__(256)
ep_k(const __half* __restrict__ ctx, const float* __restrict__ att,
     const __half* __restrict__ S1, const __half* __restrict__ X,
     __half* __restrict__ T)
{
    int e = blockIdx.x;
    int t = threadIdx.x;
    float s = 0.0f;
#pragma unroll
    for (int jj = 0; jj < 7; jj++) {
        int p = e * 7 + jj;
        s += att[p] * __half2float(ctx[(size_t)p * HCTX + t]);
    }
    T[(size_t)e * HTOT + 256 + t] = __float2half(s);
    T[(size_t)e * HTOT + t]       = S1[(size_t)e * HENC + t];
    T[(size_t)e * HTOT + 512 + t] = X[(size_t)e * HIN + t];
    T[(size_t)e * HTOT + 768 + t] = X[(size_t)e * HIN + 256 + t];
}

extern "C" void kernel_launch(void* const* d_in, const int* in_sizes, int n_in,
                              void* d_out, int out_size)
{
    const float* inputs = (const float*)d_in[0];
    const float* state  = (const float*)d_in[1];
    const float* W_in   = (const float*)d_in[2];
    const float* b_in   = (const float*)d_in[3];
    const float* W_enc  = (const float*)d_in[4];
    const float* b_enc  = (const float*)d_in[5];
    const float* W_core = (const float*)d_in[6];
    const float* b_core = (const float*)d_in[7];
    const float* W_ctx  = (const float*)d_in[8];
    const float* b_ctx  = (const float*)d_in[9];
    const float* W_att  = (const float*)d_in[10];
    const float* b_att  = (const float*)d_in[11];
    const float* W_rec  = (const float*)d_in[12];
    const float* b_rec  = (const float*)d_in[13];
    const float* W_out  = (const float*)d_in[14];
    const float* b_out  = (const float*)d_in[15];

    float* out       = (float*)d_out;
    float* new_state = (float*)d_out + (size_t)BENT * MDIM;

    __half *pInh, *pSth, *pWinh, *pWench, *pWcath, *pWctxh, *pWrech, *pWouth;
    __half *pXh, *pS1h, *pCFh, *pCoreh, *pCtxh, *pTh, *pNSh;
    float  *pAtt;
    cudaGetSymbolAddress((void**)&pInh,    g_inh);
    cudaGetSymbolAddress((void**)&pSth,    g_sth);
    cudaGetSymbolAddress((void**)&pWinh,   g_Winh);
    cudaGetSymbolAddress((void**)&pWench,  g_Wench);
    cudaGetSymbolAddress((void**)&pWcath,  g_Wcath);
    cudaGetSymbolAddress((void**)&pWctxh,  g_Wctxh);
    cudaGetSymbolAddress((void**)&pWrech,  g_Wrech);
    cudaGetSymbolAddress((void**)&pWouth,  g_Wouth);
    cudaGetSymbolAddress((void**)&pXh,     g_Xh);
    cudaGetSymbolAddress((void**)&pS1h,    g_S1h);
    cudaGetSymbolAddress((void**)&pCFh,    g_CFh);
    cudaGetSymbolAddress((void**)&pCoreh,  g_coreh);
    cudaGetSymbolAddress((void**)&pCtxh,   g_ctxh);
    cudaGetSymbolAddress((void**)&pAtt,    g_att);
    cudaGetSymbolAddress((void**)&pTh,     g_Th);
    cudaGetSymbolAddress((void**)&pNSh,    g_NSh);

    cudaFuncSetAttribute(hgemm_g<1,0>, cudaFuncAttributeMaxDynamicSharedMemorySize, SMEMG);
    cudaFuncSetAttribute(hgemm_g<0,0>, cudaFuncAttributeMaxDynamicSharedMemorySize, SMEMG);
    cudaFuncSetAttribute(hgemm_g<2,2>, cudaFuncAttributeMaxDynamicSharedMemorySize, SMEMG);
    cudaFuncSetAttribute(hgemm_g<2,1>, cudaFuncAttributeMaxDynamicSharedMemorySize, SMEMG);
    cudaFuncSetAttribute(fused_xc,     cudaFuncAttributeMaxDynamicSharedMemorySize, SMEMG);

    // 0) fused fp32 -> fp16 conversions (W_core repacked to [Wtop|Wbot])
    CvtArgs ca;
    ca.s[0] = inputs; ca.d[0] = pInh;
    ca.s[1] = state;  ca.d[1] = pSth;
    ca.s[2] = W_in;   ca.d[2] = pWinh;
    ca.s[3] = W_enc;  ca.d[3] = pWench;
    ca.s[4] = W_core; ca.d[4] = pWcath;
    ca.s[5] = W_ctx;  ca.d[5] = pWctxh;
    ca.s[6] = W_rec;  ca.d[6] = pWrech;
    ca.s[7] = W_out;  ca.d[7] = pWouth;
    cvtall_k<<<11776, 256>>>(ca);

    // 1) S1 = relu(state @ W_enc)          [4096,256]  K=512
    hgemm_g<1,0><<<dim3(HENC/128, BENT/128), 256, SMEMG>>>(pSth, pWench, b_enc, pS1h, nullptr, HENC, HSTATE);
    // 2) CF = S1 @ [Wtop|Wbot]             [4096,1024] K=256, fp16 out, no bias
    hgemm_g<0,0><<<dim3(1024/128, BENT/128), 256, SMEMG>>>(pS1h, pWcath, nullptr, pCFh, nullptr, 1024, HENC);
    // 3) core[p]=relu(CF[rcs,:512]+CF[rfs,512:]+b) and att[p]  (28672 blocks)
    gath_k<<<NPAIR, 128>>>(pCFh, b_core, W_att, b_att, pCoreh, pAtt);
    // 4) fused: X GEMM (128 CTAs, first) + ctx GEMM (448 CTAs)
    fused_xc<<<576, 256, SMEMG>>>(pInh, pWinh, b_in, pXh,
                                  pCoreh, pWctxh, b_ctx, pCtxh);
    // 5) fused E-sum + pack T              [4096,1024]
    ep_k<<<BENT, 256>>>(pCtxh, pAtt, pS1h, pXh, pTh);
    // 6) new_state = sigmoid(T @ W_rec)    [4096,512]  K=1024, fp32+fp16
    hgemm_g<2,2><<<dim3(HSTATE/128, BENT/128), 256, SMEMG>>>(pTh, pWrech, b_rec, pNSh, new_state, HSTATE, HTOT);
    // 7) out = sigmoid(new_state @ W_out)  [4096,4096] K=512, fp32
    hgemm_g<2,1><<<dim3(MDIM/128, BENT/128), 256, SMEMG>>>(pNSh, pWouth, b_out, nullptr, out, MDIM, HSTATE);
}

// round 17
// speedup vs baseline: 1.1388x; 1.1388x over previous
#include <cuda_runtime.h>
#include <cuda_fp16.h>
#include <math.h>
#include <stdint.h>

// Problem dims (fixed)
#define KENT    8
#define BENT    4096
#define MDIM    4096
#define HIN     512
#define HENC    256
#define HCORE   512
#define HCTX    256
#define HSTATE  512
#define NPAIR   (BENT * (KENT - 1))   // 28672
#define HTOT    (HENC + HCTX + HIN)   // 1024

// ---- scratch (no allocation allowed) ----
__device__ __half g_inh[(size_t)BENT * MDIM];
__device__ __half g_sth[BENT * HSTATE];
__device__ __half g_Winh[MDIM * HIN];
__device__ __half g_Wench[HSTATE * HENC];
__device__ __half g_Wcath[HENC * (2 * HCORE)];     // [256,1024] = [Wtop | Wbot]
__device__ __half g_Wctxh[HCORE * HCTX];
__device__ __half g_Wrech[HTOT * HSTATE];
__device__ __half g_Wouth[HSTATE * MDIM];
__device__ __half g_Xh[BENT * HIN];
__device__ __half g_S1h[BENT * HENC];
__device__ __half g_CFh[(size_t)BENT * 2 * HCORE]; // [4096,1024] fp16, 8 MB
__device__ __half g_coreh[(size_t)NPAIR * HCORE];
__device__ __half g_ctxh[(size_t)NPAIR * HCTX];
__device__ float  g_att[NPAIR];
__device__ __half g_Th[BENT * HTOT];
__device__ __half g_NSh[BENT * HSTATE];

template<int ACT>
__device__ __forceinline__ float actf(float v) {
    if (ACT == 1) return fmaxf(v, 0.0f);                  // relu
    if (ACT == 2) return 1.0f / (1.0f + __expf(-v));      // sigmoid (fast exp)
    if (ACT == 3) return v > 0.0f ? v : expm1f(v);        // elu
    return v;                                             // 0: identity (no bias)
}

// ---- fused fp32->fp16 conversion over 8 fixed segments ----
// seg 4 (W_core) repacked: row k (0..511), col n -> Wcat[(k&255)*1024 + (k>>8)*512 + n]
struct CvtArgs { const float* s[8]; __half* d[8]; };

__global__ void __launch_bounds__(256)
cvtall_k(CvtArgs a)
{
    long long i = ((long long)blockIdx.x * 256 + threadIdx.x) * 8;
    int seg; long long off;
    if      (i < 16777216LL) { seg = 0; off = i; }
    else if (i < 18874368LL) { seg = 1; off = i - 16777216LL; }
    else if (i < 20971520LL) { seg = 2; off = i - 18874368LL; }
    else if (i < 21102592LL) { seg = 3; off = i - 20971520LL; }
    else if (i < 21364736LL) { seg = 4; off = i - 21102592LL; }
    else if (i < 21495808LL) { seg = 5; off = i - 21364736LL; }
    else if (i < 22020096LL) { seg = 6; off = i - 21495808LL; }
    else if (i < 24117248LL) { seg = 7; off = i - 22020096LL; }
    else return;
    const float* s = a.s[seg] + off;
    long long doff = off;
    if (seg == 4) {
        long long k = off >> 9, n = off & 511;
        doff = (k & 255) * 1024 + (k >> 8) * 512 + n;
    }
    __half* d = a.d[seg] + doff;
    float4 x = *(const float4*)s;
    float4 y = *(const float4*)(s + 4);
    __half2 h0 = __floats2half2_rn(x.x, x.y);
    __half2 h1 = __floats2half2_rn(x.z, x.w);
    __half2 h2 = __floats2half2_rn(y.x, y.y);
    __half2 h3 = __floats2half2_rn(y.z, y.w);
    uint4 o;
    o.x = *(uint32_t*)&h0; o.y = *(uint32_t*)&h1;
    o.z = *(uint32_t*)&h2; o.w = *(uint32_t*)&h3;
    *(uint4*)d = o;
}

// ---- GEMM tiling (proven): BK=32, 4-stage cp.async pipeline ----
#define STAGES 4
#define ASTR 80
#define BSTR 272
#define BBUF (32 * BSTR)              // 8704
#define ABUF (128 * ASTR)             // 10240
#define STGB (ABUF + BBUF)
#define SMEMG (STAGES * STGB)         // 75776

__device__ __forceinline__ void cp16(uint32_t dst, const void* src) {
    asm volatile("cp.async.cg.shared.global [%0], [%1], 16;" :: "r"(dst), "l"(src));
}

// fp16 tensor-core GEMM: 128x128 CTA tile, BK=32, 256 threads, 8 warps 2x4,
// warp tile 64x32 (m16n8k16), fp32 accum.
// ACT 0: identity, NO bias. WOUT 0: fp16 C. 1: fp32 C. 2: both.
template<int ACT, int WOUT>
__global__ void __launch_bounds__(256, 2)
hgemm_g(const __half* __restrict__ A, const __half* __restrict__ B,
        const float* __restrict__ bias, __half* __restrict__ Ch,
        float* __restrict__ Cf, int N, int K)
{
    extern __shared__ char sm[];
    const uint32_t smb = (uint32_t)__cvta_generic_to_shared(sm);

    const int tid  = threadIdx.x;
    const int warp = tid >> 5;
    const int lane = tid & 31;
    const int row0 = blockIdx.y * 128;
    const int col0 = blockIdx.x * 128;

    const int wm = warp >> 2, wn = warp & 3;
    const int m_base = wm * 64, n_base = wn * 32;
    const int grp = lane >> 2, tg = lane & 3;

    const int a_row = (lane & 7) + ((lane >> 3) & 1) * 8;
    const int a_kh  = (lane >> 4) * 8;
    const uint32_t aLane = (uint32_t)((m_base + a_row) * ASTR + a_kh * 2);
    const int b_k  = (lane & 7) + ((lane >> 3) & 1) * 8;
    const int b_nh = (lane >> 4) * 8;
    const uint32_t bLane = (uint32_t)(b_k * BSTR + (n_base + b_nh) * 2);

    const int arow = tid >> 1;
    const int ak16 = (tid & 1) * 16;
    const uint32_t aoff = (uint32_t)(arow * ASTR + ak16 * 2);
    const __half* aBase = A + (size_t)(row0 + arow) * K + ak16;
    const int brow = tid >> 3;
    const int bo16 = (tid & 7) * 16;
    const uint32_t boff = (uint32_t)(brow * BSTR + bo16 * 2);
    const __half* bBase = B + (size_t)brow * N + col0 + bo16;

    auto issue_stage = [&](int s, int kg) {
        uint32_t ab = smb + (uint32_t)s * STGB;
        uint32_t bb = ab + ABUF;
        const __half* asrc = aBase + kg;
        cp16(ab + aoff, asrc);
        cp16(ab + aoff + 16, asrc + 8);
        const __half* bsrc = bBase + (size_t)kg * N;
        cp16(bb + boff, bsrc);
        cp16(bb + boff + 16, bsrc + 8);
    };

    float acc[4][4][4];
#pragma unroll
    for (int mt = 0; mt < 4; mt++)
#pragma unroll
        for (int nt = 0; nt < 4; nt++)
#pragma unroll
            for (int c = 0; c < 4; c++) acc[mt][nt][c] = 0.0f;

    const int nk = K >> 5;

#pragma unroll
    for (int s = 0; s < STAGES - 1; s++) {
        if (s < nk) issue_stage(s, s << 5);
        asm volatile("cp.async.commit_group;" ::: "memory");
    }

    for (int it = 0; it < nk; ++it) {
        asm volatile("cp.async.wait_group %0;" :: "n"(STAGES - 2) : "memory");
        __syncthreads();
        const int nxt = it + STAGES - 1;
        if (nxt < nk) issue_stage(nxt & (STAGES - 1), nxt << 5);
        asm volatile("cp.async.commit_group;" ::: "memory");

        const uint32_t ab = smb + (uint32_t)(it & (STAGES - 1)) * STGB + aLane;
        const uint32_t bb = smb + (uint32_t)(it & (STAGES - 1)) * STGB + ABUF + bLane;
#pragma unroll
        for (int ks = 0; ks < 2; ks++) {
            uint32_t af[4][4];
#pragma unroll
            for (int mt = 0; mt < 4; mt++) {
                uint32_t addr = ab + mt * (16 * ASTR) + ks * 32;
                asm volatile("ldmatrix.sync.aligned.m8n8.x4.shared.b16 {%0,%1,%2,%3}, [%4];"
                             : "=r"(af[mt][0]), "=r"(af[mt][1]),
                               "=r"(af[mt][2]), "=r"(af[mt][3])
                             : "r"(addr));
            }
            uint32_t bf[4][2];
#pragma unroll
            for (int nl = 0; nl < 2; nl++) {
                uint32_t addr = bb + nl * 32 + ks * (16 * BSTR);
                asm volatile("ldmatrix.sync.aligned.m8n8.x4.trans.shared.b16 {%0,%1,%2,%3}, [%4];"
                             : "=r"(bf[nl*2][0]), "=r"(bf[nl*2][1]),
                               "=r"(bf[nl*2+1][0]), "=r"(bf[nl*2+1][1])
                             : "r"(addr));
            }
#pragma unroll
            for (int mt = 0; mt < 4; mt++) {
#pragma unroll
                for (int nt = 0; nt < 4; nt++) {
                    asm("mma.sync.aligned.m16n8k16.row.col.f32.f16.f16.f32 "
                        "{%0,%1,%2,%3}, {%4,%5,%6,%7}, {%8,%9}, {%0,%1,%2,%3};"
                        : "+f"(acc[mt][nt][0]), "+f"(acc[mt][nt][1]),
                          "+f"(acc[mt][nt][2]), "+f"(acc[mt][nt][3])
                        : "r"(af[mt][0]), "r"(af[mt][1]), "r"(af[mt][2]), "r"(af[mt][3]),
                          "r"(bf[nt][0]), "r"(bf[nt][1]));
                }
            }
        }
    }

#pragma unroll
    for (int nt = 0; nt < 4; nt++) {
        int col = col0 + n_base + nt * 8 + 2 * tg;
        float2 bb2;
        if (ACT == 0) { bb2.x = 0.0f; bb2.y = 0.0f; }
        else          { bb2 = *(const float2*)(bias + col); }
#pragma unroll
        for (int mt = 0; mt < 4; mt++) {
            int row = row0 + m_base + mt * 16 + grp;
            float v00 = actf<ACT>(acc[mt][nt][0] + bb2.x);
            float v01 = actf<ACT>(acc[mt][nt][1] + bb2.y);
            float v10 = actf<ACT>(acc[mt][nt][2] + bb2.x);
            float v11 = actf<ACT>(acc[mt][nt][3] + bb2.y);
            if (WOUT != 1) {
                __half2 h0 = __floats2half2_rn(v00, v01);
                __half2 h1 = __floats2half2_rn(v10, v11);
                *(__half2*)(Ch + (size_t)row * N + col) = h0;
                *(__half2*)(Ch + (size_t)(row + 8) * N + col) = h1;
            }
            if (WOUT != 0) {
                float2 f0 = {v00, v01}, f1 = {v10, v11};
                *(float2*)(Cf + (size_t)row * N + col) = f0;
                *(float2*)(Cf + (size_t)(row + 8) * N + col) = f1;
            }
        }
    }
}

// gather + attention v2: one block per entity-slot (b,i), handling its 7
// pairs. frow/b_core/W_att loaded once and reused 7x. 128 threads, 4 elem/t.
// core[p,:] = relu(CF[rcs,0:512] + CF[rfs,512:1024] + b_core)
// att[p] = sigmoid(core[p,:] . W_att + b_att)
__global__ void __launch_bounds__(128)
gath_k(const __half* __restrict__ CF, const float* __restrict__ b_core,
       const float* __restrict__ W_att, const float* __restrict__ b_att,
       __half* __restrict__ core, float* __restrict__ att)
{
    __shared__ float red[7][4];
    int e = blockIdx.x;                   // 0..4095 = b*8 + i
    int t = threadIdx.x;                  // 0..127, elems 4t..4t+3
    int b_ = e >> 3;
    int i_ = e & 7;

    // invariant loads
    const __half* frow = CF + (size_t)e * 1024 + 512;
    uint2 fu = *(const uint2*)(frow + 4 * t);
    float2 f0 = __half22float2(*(__half2*)&fu.x);
    float2 f1 = __half22float2(*(__half2*)&fu.y);
    float4 bb = *(const float4*)(b_core + 4 * t);
    float4 w  = *(const float4*)(W_att + 4 * t);
    float fb0 = f0.x + bb.x, fb1 = f0.y + bb.y;
    float fb2 = f1.x + bb.z, fb3 = f1.y + bb.w;
    int warp = t >> 5;
    size_t pbase = (size_t)(b_ * 56 + i_ * 7);

#pragma unroll
    for (int jj = 0; jj < 7; jj++) {
        int j_ = jj + (jj >= i_ ? 1 : 0);
        const __half* crow = CF + (size_t)(b_ * KENT + j_) * 1024;
        uint2 cu = *(const uint2*)(crow + 4 * t);
        float2 c0 = __half22float2(*(__half2*)&cu.x);
        float2 c1 = __half22float2(*(__half2*)&cu.y);
        float v0 = fmaxf(c0.x + fb0, 0.0f);
        float v1 = fmaxf(c0.y + fb1, 0.0f);
        float v2 = fmaxf(c1.x + fb2, 0.0f);
        float v3 = fmaxf(c1.y + fb3, 0.0f);
        __half2 o0 = __floats2half2_rn(v0, v1);
        __half2 o1 = __floats2half2_rn(v2, v3);
        uint2 ov;
        ov.x = *(uint32_t*)&o0; ov.y = *(uint32_t*)&o1;
        *(uint2*)(core + (pbase + jj) * HCORE + 4 * t) = ov;

        float s = v0 * w.x + v1 * w.y + v2 * w.z + v3 * w.w;
#pragma unroll
        for (int o = 16; o; o >>= 1) s += __shfl_xor_sync(0xFFFFFFFFu, s, o);
        if ((t & 31) == 0) red[jj][warp] = s;
    }
    __syncthreads();
    if (t < 7) {
        float tot = red[t][0] + red[t][1] + red[t][2] + red[t][3];
        att[pbase + t] = 1.0f / (1.0f + __expf(-(tot + b_att[0])));
    }
}

// fused: E = sum_j att*ctx, then T = [S1 | E | X]
__global__ void __launch_bounds__(256)
ep_k(const __half* __restrict__ ctx, const float* __restrict__ att,
     const __half* __restrict__ S1, const __half* __restrict__ X,
     __half* __restrict__ T)
{
    int e = blockIdx.x;
    int t = threadIdx.x;
    float s = 0.0f;
#pragma unroll
    for (int jj = 0; jj < 7; jj++) {
        int p = e * 7 + jj;
        s += att[p] * __half2float(ctx[(size_t)p * HCTX + t]);
    }
    T[(size_t)e * HTOT + 256 + t] = __float2half(s);
    T[(size_t)e * HTOT + t]       = S1[(size_t)e * HENC + t];
    T[(size_t)e * HTOT + 512 + t] = X[(size_t)e * HIN + t];
    T[(size_t)e * HTOT + 768 + t] = X[(size_t)e * HIN + 256 + t];
}

extern "C" void kernel_launch(void* const* d_in, const int* in_sizes, int n_in,
                              void* d_out, int out_size)
{
    const float* inputs = (const float*)d_in[0];
    const float* state  = (const float*)d_in[1];
    const float* W_in   = (const float*)d_in[2];
    const float* b_in   = (const float*)d_in[3];
    const float* W_enc  = (const float*)d_in[4];
    const float* b_enc  = (const float*)d_in[5];
    const float* W_core = (const float*)d_in[6];
    const float* b_core = (const float*)d_in[7];
    const float* W_ctx  = (const float*)d_in[8];
    const float* b_ctx  = (const float*)d_in[9];
    const float* W_att  = (const float*)d_in[10];
    const float* b_att  = (const float*)d_in[11];
    const float* W_rec  = (const float*)d_in[12];
    const float* b_rec  = (const float*)d_in[13];
    const float* W_out  = (const float*)d_in[14];
    const float* b_out  = (const float*)d_in[15];

    float* out       = (float*)d_out;
    float* new_state = (float*)d_out + (size_t)BENT * MDIM;

    __half *pInh, *pSth, *pWinh, *pWench, *pWcath, *pWctxh, *pWrech, *pWouth;
    __half *pXh, *pS1h, *pCFh, *pCoreh, *pCtxh, *pTh, *pNSh;
    float  *pAtt;
    cudaGetSymbolAddress((void**)&pInh,    g_inh);
    cudaGetSymbolAddress((void**)&pSth,    g_sth);
    cudaGetSymbolAddress((void**)&pWinh,   g_Winh);
    cudaGetSymbolAddress((void**)&pWench,  g_Wench);
    cudaGetSymbolAddress((void**)&pWcath,  g_Wcath);
    cudaGetSymbolAddress((void**)&pWctxh,  g_Wctxh);
    cudaGetSymbolAddress((void**)&pWrech,  g_Wrech);
    cudaGetSymbolAddress((void**)&pWouth,  g_Wouth);
    cudaGetSymbolAddress((void**)&pXh,     g_Xh);
    cudaGetSymbolAddress((void**)&pS1h,    g_S1h);
    cudaGetSymbolAddress((void**)&pCFh,    g_CFh);
    cudaGetSymbolAddress((void**)&pCoreh,  g_coreh);
    cudaGetSymbolAddress((void**)&pCtxh,   g_ctxh);
    cudaGetSymbolAddress((void**)&pAtt,    g_att);
    cudaGetSymbolAddress((void**)&pTh,     g_Th);
    cudaGetSymbolAddress((void**)&pNSh,    g_NSh);

    cudaFuncSetAttribute(hgemm_g<3,0>, cudaFuncAttributeMaxDynamicSharedMemorySize, SMEMG);
    cudaFuncSetAttribute(hgemm_g<1,0>, cudaFuncAttributeMaxDynamicSharedMemorySize, SMEMG);
    cudaFuncSetAttribute(hgemm_g<0,0>, cudaFuncAttributeMaxDynamicSharedMemorySize, SMEMG);
    cudaFuncSetAttribute(hgemm_g<2,2>, cudaFuncAttributeMaxDynamicSharedMemorySize, SMEMG);
    cudaFuncSetAttribute(hgemm_g<2,1>, cudaFuncAttributeMaxDynamicSharedMemorySize, SMEMG);

    // 0) fused fp32 -> fp16 conversions (W_core repacked to [Wtop|Wbot])
    CvtArgs ca;
    ca.s[0] = inputs; ca.d[0] = pInh;
    ca.s[1] = state;  ca.d[1] = pSth;
    ca.s[2] = W_in;   ca.d[2] = pWinh;
    ca.s[3] = W_enc;  ca.d[3] = pWench;
    ca.s[4] = W_core; ca.d[4] = pWcath;
    ca.s[5] = W_ctx;  ca.d[5] = pWctxh;
    ca.s[6] = W_rec;  ca.d[6] = pWrech;
    ca.s[7] = W_out;  ca.d[7] = pWouth;
    cvtall_k<<<11776, 256>>>(ca);

    // 1) X = elu(inputs @ W_in)            [4096,512]  K=4096
    hgemm_g<3,0><<<dim3(HIN/128, BENT/128), 256, SMEMG>>>(pInh, pWinh, b_in, pXh, nullptr, HIN, MDIM);
    // 2) S1 = relu(state @ W_enc)          [4096,256]  K=512
    hgemm_g<1,0><<<dim3(HENC/128, BENT/128), 256, SMEMG>>>(pSth, pWench, b_enc, pS1h, nullptr, HENC, HSTATE);
    // 3) CF = S1 @ [Wtop|Wbot]             [4096,1024] K=256, fp16 out, no bias
    hgemm_g<0,0><<<dim3(1024/128, BENT/128), 256, SMEMG>>>(pS1h, pWcath, nullptr, pCFh, nullptr, 1024, HENC);
    // 4) gather+att: one block per entity-slot (4096 blocks, 7 pairs each)
    gath_k<<<BENT, 128>>>(pCFh, b_core, W_att, b_att, pCoreh, pAtt);
    // 5) ctx = relu(core @ W_ctx)          [28672,256] K=512
    hgemm_g<1,0><<<dim3(HCTX/128, NPAIR/128), 256, SMEMG>>>(pCoreh, pWctxh, b_ctx, pCtxh, nullptr, HCTX, HCORE);
    // 6) fused E-sum + pack T              [4096,1024]
    ep_k<<<BENT, 256>>>(pCtxh, pAtt, pS1h, pXh, pTh);
    // 7) new_state = sigmoid(T @ W_rec)    [4096,512]  K=1024, fp32+fp16
    hgemm_g<2,2><<<dim3(HSTATE/128, BENT/128), 256, SMEMG>>>(pTh, pWrech, b_rec, pNSh, new_state, HSTATE, HTOT);
    // 8) out = sigmoid(new_state @ W_out)  [4096,4096] K=512, fp32
    hgemm_g<2,1><<<dim3(MDIM/128, BENT/128), 256, SMEMG>>>(pNSh, pWouth, b_out, nullptr, out, MDIM, HSTATE);
}